// round 1
// baseline (speedup 1.0000x reference)
#include <cuda_runtime.h>
#include <math.h>

// Problem constants
#define BB 128          // batch
#define SS 512          // sequence length
#define II 256          // input size
#define HH 1024         // hidden size
#define NC 10           // classes

// Tiling
#define TK 16           // k-tile
#define TNH 8           // h-columns per block (x4 gates = 32 gate cols)
#define NTHREADS 128

// Persistent state (allocation-free scratch)
__device__ float g_h[2][BB * HH];
__device__ float g_c[BB * HH];

__device__ __forceinline__ float sigmoidf_(float v) {
    return 1.0f / (1.0f + expf(-v));
}

__global__ void init_kernel(const float* __restrict__ h0,
                            const float* __restrict__ c0) {
    int i = blockIdx.x * blockDim.x + threadIdx.x;
    if (i < BB * HH) {
        g_h[0][i] = h0[i];
        g_c[i] = c0[i];
    }
}

// One LSTM timestep, fully fused:
//   gates[b, j] = sum_i x[b,s,i] * W_ih[j,i] + sum_k h[b,k] * W_hh[j,k] + b_ih[j] + b_hh[j]
//   i,f,g,o split -> activations -> c,h update.
// Block = 128 threads. Block tile: 128 (batch) x 32 (8 h-cols x 4 gates).
// Thread micro-tile: 8m x 4n = 32 accumulators.
__global__ __launch_bounds__(NTHREADS) void step_kernel(
    const float* __restrict__ x,
    const float* __restrict__ W_ih,
    const float* __restrict__ W_hh,
    const float* __restrict__ b_ih,
    const float* __restrict__ b_hh,
    int s, int src)
{
    __shared__ float sA[TK][132];      // A tile, transposed [k][m], pad for banks
    __shared__ float sB[TK][36];       // B tile [k][n], n = gate*8 + hcol
    __shared__ float sG[BB][33];       // gates exchange buffer

    const int tid = threadIdx.x;
    const int n0 = blockIdx.x * TNH;   // h-column offset for this block
    const float* __restrict__ h_in = g_h[src];
    float* __restrict__ h_out = g_h[src ^ 1];

    float acc[8][4];
#pragma unroll
    for (int i = 0; i < 8; i++)
#pragma unroll
        for (int j = 0; j < 4; j++) acc[i][j] = 0.0f;

    const int m_thr = (tid & 15) * 8;   // 16 groups x 8 rows = 128
    const int n_thr = (tid >> 4) * 4;   // 8 groups x 4 cols = 32
    const int lk = tid & 15;            // k-lane for tile loads (coalesced)
    const int lg = tid >> 4;            // 0..7 row/col group for tile loads

    // ---------------- Phase 1: x @ W_ih^T (K = II = 256) ----------------
    {
        const float* xs = x + s * II;   // x[b, s, i] = xs[b*SS*II + i]
        for (int k0 = 0; k0 < II; k0 += TK) {
            __syncthreads();
#pragma unroll
            for (int p = 0; p < 16; p++) {
                int m = lg * 16 + p;
                sA[lk][m] = xs[m * SS * II + k0 + lk];
            }
#pragma unroll
            for (int q = 0; q < 4; q++) {
                int n = q * 8 + lg;
                int j = q * HH + n0 + lg;
                sB[lk][n] = W_ih[j * II + k0 + lk];
            }
            __syncthreads();
#pragma unroll
            for (int k = 0; k < TK; k++) {
                float4 a0 = *(const float4*)&sA[k][m_thr];
                float4 a1 = *(const float4*)&sA[k][m_thr + 4];
                float4 bb = *(const float4*)&sB[k][n_thr];
                float av[8] = {a0.x, a0.y, a0.z, a0.w, a1.x, a1.y, a1.z, a1.w};
                float bv[4] = {bb.x, bb.y, bb.z, bb.w};
#pragma unroll
                for (int mm = 0; mm < 8; mm++)
#pragma unroll
                    for (int nn = 0; nn < 4; nn++)
                        acc[mm][nn] = fmaf(av[mm], bv[nn], acc[mm][nn]);
            }
        }
    }

    // ---------------- Phase 2: h @ W_hh^T (K = HH = 1024) ----------------
    for (int k0 = 0; k0 < HH; k0 += TK) {
        __syncthreads();
#pragma unroll
        for (int p = 0; p < 16; p++) {
            int m = lg * 16 + p;
            sA[lk][m] = h_in[m * HH + k0 + lk];
        }
#pragma unroll
        for (int q = 0; q < 4; q++) {
            int n = q * 8 + lg;
            int j = q * HH + n0 + lg;
            sB[lk][n] = W_hh[j * HH + k0 + lk];
        }
        __syncthreads();
#pragma unroll
        for (int k = 0; k < TK; k++) {
            float4 a0 = *(const float4*)&sA[k][m_thr];
            float4 a1 = *(const float4*)&sA[k][m_thr + 4];
            float4 bb = *(const float4*)&sB[k][n_thr];
            float av[8] = {a0.x, a0.y, a0.z, a0.w, a1.x, a1.y, a1.z, a1.w};
            float bv[4] = {bb.x, bb.y, bb.z, bb.w};
#pragma unroll
            for (int mm = 0; mm < 8; mm++)
#pragma unroll
                for (int nn = 0; nn < 4; nn++)
                    acc[mm][nn] = fmaf(av[mm], bv[nn], acc[mm][nn]);
        }
    }

    // ---------------- Gate exchange + elementwise update ----------------
    __syncthreads();
#pragma unroll
    for (int mm = 0; mm < 8; mm++)
#pragma unroll
        for (int nn = 0; nn < 4; nn++)
            sG[m_thr + mm][n_thr + nn] = acc[mm][nn];
    __syncthreads();

    // 128 batch x 8 h-cols = 1024 elements -> 8 per thread, coalesced by (b, hc)
#pragma unroll
    for (int e = 0; e < 8; e++) {
        int p = e * NTHREADS + tid;
        int b = p >> 3;         // batch row
        int hc = p & 7;         // local h-column
        int jn = n0 + hc;       // global h index
        float iraw = sG[b][hc]       + b_ih[jn]          + b_hh[jn];
        float fraw = sG[b][8 + hc]   + b_ih[HH + jn]     + b_hh[HH + jn];
        float graw = sG[b][16 + hc]  + b_ih[2 * HH + jn] + b_hh[2 * HH + jn];
        float oraw = sG[b][24 + hc]  + b_ih[3 * HH + jn] + b_hh[3 * HH + jn];
        int idx = b * HH + jn;
        float c_old = g_c[idx];
        float ig = sigmoidf_(iraw);
        float fg = sigmoidf_(fraw);
        float gg = tanhf(graw);
        float og = sigmoidf_(oraw);
        float c_new = fg * c_old + ig * gg;
        g_c[idx] = c_new;
        h_out[idx] = og * tanhf(c_new);
    }
}

// out[b, c] = h_last[b, :] . W_out[c, :] + b_out[c]
__global__ void head_kernel(const float* __restrict__ W_out,
                            const float* __restrict__ b_out,
                            float* __restrict__ out, int src) {
    int b = blockIdx.x;
    int c = blockIdx.y;
    int lane = threadIdx.x;
    const float* h = g_h[src] + b * HH;
    const float* w = W_out + c * HH;
    float sum = 0.0f;
    for (int k = lane; k < HH; k += 32)
        sum = fmaf(h[k], w[k], sum);
#pragma unroll
    for (int off = 16; off > 0; off >>= 1)
        sum += __shfl_down_sync(0xFFFFFFFFu, sum, off);
    if (lane == 0) out[b * NC + c] = sum + b_out[c];
}

extern "C" void kernel_launch(void* const* d_in, const int* in_sizes, int n_in,
                              void* d_out, int out_size) {
    const float* x     = (const float*)d_in[0];   // (128, 512, 256)
    const float* h0    = (const float*)d_in[1];   // (128, 1024)
    const float* c0    = (const float*)d_in[2];   // (128, 1024)
    const float* W_ih  = (const float*)d_in[3];   // (4096, 256)
    const float* W_hh  = (const float*)d_in[4];   // (4096, 1024)
    const float* b_ih  = (const float*)d_in[5];   // (4096,)
    const float* b_hh  = (const float*)d_in[6];   // (4096,)
    const float* W_out = (const float*)d_in[7];   // (10, 1024)
    const float* b_out = (const float*)d_in[8];   // (10,)
    float* out = (float*)d_out;                   // (128, 10)

    init_kernel<<<256, 512>>>(h0, c0);

    for (int s = 0; s < SS; s++) {
        step_kernel<<<HH / TNH, NTHREADS>>>(x, W_ih, W_hh, b_ih, b_hh, s, s & 1);
    }

    // After 512 steps (even count), h_last lives in g_h[0]
    head_kernel<<<dim3(BB, NC), 32>>>(W_out, b_out, out, 0);
}

// round 3
// speedup vs baseline: 2.7085x; 2.7085x over previous
#include <cuda_runtime.h>
#include <cuda_fp16.h>
#include <math.h>
#include <stdint.h>

// ------------------------------------------------------------------
// Problem constants
// ------------------------------------------------------------------
#define BB 128          // batch (GEMM M)
#define SS 512          // sequence length
#define II 256          // input size
#define HH 1024         // hidden size
#define NC 10           // classes
#define KTOT 1280       // K = HH + II
#define NTOT 4096       // 4*HH gate columns

#define NCTA 64         // CTAs per step
#define NTHREADS 256    // 8 warps
#define CTA_N 64        // gate columns per CTA (4 gates x 16 h-cols)
#define KC 64           // K elements per pipeline stage
#define NCHUNK (KTOT / KC)   // 20
#define NSTAGE 3

// Stage smem layout (bytes): Ah 16K | Al 16K | Bh 8K | Bl 8K = 48K
#define ST_AH 0
#define ST_AL 16384
#define ST_BH 32768
#define ST_BL 40960
#define STAGE_BYTES 49152
#define SMEM_NEED (NSTAGE * STAGE_BYTES)
#define SG_PITCH 66

// ------------------------------------------------------------------
// Persistent device scratch (allocation-free)
// ------------------------------------------------------------------
__device__ __align__(16) __half g_Whi[NTOT * KTOT];   // permuted [n'][k]
__device__ __align__(16) __half g_Wlo[NTOT * KTOT];
__device__ __align__(16) __half g_xhi[SS * BB * II];  // [s][b][i]
__device__ __align__(16) __half g_xlo[SS * BB * II];
__device__ __align__(16) __half g_hhi[2][BB * HH];
__device__ __align__(16) __half g_hlo[2][BB * HH];
__device__ float g_c[BB * HH];
__device__ float g_bias[NTOT];

// ------------------------------------------------------------------
// PTX helpers (all baseline compute_103 features: sm_80-era)
// ------------------------------------------------------------------
__device__ __forceinline__ uint32_t smem_u32(const void* p) {
    uint32_t a;
    asm("{ .reg .u64 t; cvta.to.shared.u64 t, %1; cvt.u32.u64 %0, t; }"
        : "=r"(a) : "l"(p));
    return a;
}

__device__ __forceinline__ void cp_async16(uint32_t saddr, const void* gaddr) {
    asm volatile("cp.async.cg.shared.global [%0], [%1], 16;"
                 :: "r"(saddr), "l"(gaddr) : "memory");
}
__device__ __forceinline__ void cp_commit() {
    asm volatile("cp.async.commit_group;" ::: "memory");
}
__device__ __forceinline__ void cp_wait1() {
    asm volatile("cp.async.wait_group 1;" ::: "memory");
}
__device__ __forceinline__ void cp_wait0() {
    asm volatile("cp.async.wait_group 0;" ::: "memory");
}

__device__ __forceinline__ void ldsm_x4(uint32_t* r, uint32_t addr) {
    asm volatile("ldmatrix.sync.aligned.m8n8.x4.shared.b16 {%0,%1,%2,%3}, [%4];"
                 : "=r"(r[0]), "=r"(r[1]), "=r"(r[2]), "=r"(r[3]) : "r"(addr));
}

__device__ __forceinline__ void mma16816(float* d, const uint32_t* a,
                                         uint32_t b0, uint32_t b1) {
    asm volatile(
        "mma.sync.aligned.m16n8k16.row.col.f32.f16.f16.f32 "
        "{%0,%1,%2,%3}, {%4,%5,%6,%7}, {%8,%9}, {%0,%1,%2,%3};"
        : "+f"(d[0]), "+f"(d[1]), "+f"(d[2]), "+f"(d[3])
        : "r"(a[0]), "r"(a[1]), "r"(a[2]), "r"(a[3]), "r"(b0), "r"(b1));
}

__device__ __forceinline__ float sigmoidf_(float v) {
    return 1.0f / (1.0f + expf(-v));
}

// swizzled smem byte offset within a [rows][64 half] tile (128B rows)
__device__ __forceinline__ uint32_t sw_off(int r, int c) {   // c = 16B chunk 0..7
    return (uint32_t)(r * 128 + ((c ^ (r & 7)) << 4));
}

// ------------------------------------------------------------------
// Prep kernels (run each replay; cheap, memory-bound)
// ------------------------------------------------------------------
// Permuted, split weight matrix Wp[n'][k]:
//   n' = cta*64 + g*16 + jj  ->  weight row = g*1024 + cta*16 + jj
//   k < 1024: W_hh[row][k]; else W_ih[row][k-1024]
__global__ void prep_weights(const float* __restrict__ W_ih,
                             const float* __restrict__ W_hh) {
    int idx = blockIdx.x * blockDim.x + threadIdx.x;
    if (idx >= NTOT * KTOT) return;
    int n = idx / KTOT;
    int k = idx - n * KTOT;
    int cta = n >> 6;
    int g = (n >> 4) & 3;
    int jj = n & 15;
    int row = g * HH + cta * 16 + jj;
    float v = (k < HH) ? W_hh[row * HH + k] : W_ih[row * II + (k - HH)];
    __half hi = __float2half_rn(v);
    __half lo = __float2half_rn(v - __half2float(hi));
    g_Whi[idx] = hi;
    g_Wlo[idx] = lo;
}

// x[b][s][i] fp32 -> [s][b][i] fp16 hi/lo
__global__ void prep_x(const float* __restrict__ x) {
    int idx = blockIdx.x * blockDim.x + threadIdx.x;
    if (idx >= SS * BB * II) return;
    int s = idx / (BB * II);
    int r = idx - s * (BB * II);
    int b = r / II;
    int i = r - b * II;
    float v = x[(b * SS + s) * II + i];
    __half hi = __float2half_rn(v);
    __half lo = __float2half_rn(v - __half2float(hi));
    g_xhi[idx] = hi;
    g_xlo[idx] = lo;
}

__global__ void prep_state(const float* __restrict__ h0,
                           const float* __restrict__ c0,
                           const float* __restrict__ b_ih,
                           const float* __restrict__ b_hh) {
    int idx = blockIdx.x * blockDim.x + threadIdx.x;
    if (idx < BB * HH) {
        float v = h0[idx];
        __half hi = __float2half_rn(v);
        __half lo = __float2half_rn(v - __half2float(hi));
        g_hhi[0][idx] = hi;
        g_hlo[0][idx] = lo;
        g_c[idx] = c0[idx];
    }
    if (idx < NTOT) g_bias[idx] = b_ih[idx] + b_hh[idx];
}

// ------------------------------------------------------------------
// One LSTM timestep: HMMA split-fp16 GEMM + fused gate epilogue
//   CTA tile: M=128 (all batch) x N=64 (16 h-cols x 4 gates, permuted)
//   Warp tile: M=64 x N=16 (warps arranged 2M x 4N)
// ------------------------------------------------------------------
__global__ void __launch_bounds__(NTHREADS, 1) step_kernel(int s, int src, int dst) {
    extern __shared__ char smem_raw[];
    const uint32_t sb = smem_u32(smem_raw);

    const int tid = threadIdx.x;
    const int wid = tid >> 5;
    const int lane = tid & 31;
    const int wm = wid & 1;          // 0..1 : M group of 64
    const int wn = wid >> 1;         // 0..3 : N group of 16
    const int n0 = blockIdx.x * CTA_N;

    const __half* __restrict__ hsrc_hi = g_hhi[src];
    const __half* __restrict__ hsrc_lo = g_hlo[src];

    // ---- stage loader (cp.async, 16B chunks, swizzled) ----
    auto load_stage = [&](int chunk) {
        const uint32_t st = sb + (uint32_t)(chunk % NSTAGE) * STAGE_BYTES;
        const int k0 = chunk * KC;
        // A: 128 rows x 64 halves, hi+lo (4 chunks each per thread)
#pragma unroll
        for (int i = 0; i < 4; i++) {
            int id = tid + i * NTHREADS;       // 0..1023
            int r = id >> 3;                   // batch row
            int c = id & 7;                    // 16B chunk in row
            uint32_t d = sw_off(r, c);
            if (chunk < 16) {
                const __half* ph = hsrc_hi + r * HH + k0 + c * 8;
                const __half* pl = hsrc_lo + r * HH + k0 + c * 8;
                cp_async16(st + ST_AH + d, ph);
                cp_async16(st + ST_AL + d, pl);
            } else {
                size_t off = ((size_t)s * BB + r) * II + (k0 - HH) + c * 8;
                cp_async16(st + ST_AH + d, g_xhi + off);
                cp_async16(st + ST_AL + d, g_xlo + off);
            }
        }
        // B: 64 rows x 64 halves, hi+lo (2 chunks each per thread)
#pragma unroll
        for (int i = 0; i < 2; i++) {
            int id = tid + i * NTHREADS;       // 0..511
            int r = id >> 3;
            int c = id & 7;
            uint32_t d = sw_off(r, c);
            size_t off = (size_t)(n0 + r) * KTOT + k0 + c * 8;
            cp_async16(st + ST_BH + d, g_Whi + off);
            cp_async16(st + ST_BL + d, g_Wlo + off);
        }
        cp_commit();
    };

    // prologue: fill 2 stages
    load_stage(0);
    load_stage(1);

    float acc[4][2][4];
#pragma unroll
    for (int mt = 0; mt < 4; mt++)
#pragma unroll
        for (int nt = 0; nt < 2; nt++)
#pragma unroll
            for (int e = 0; e < 4; e++) acc[mt][nt][e] = 0.0f;

    for (int i = 0; i < NCHUNK; i++) {
        if (i == NCHUNK - 1) cp_wait0(); else cp_wait1();
        __syncthreads();

        const uint32_t st = sb + (uint32_t)(i % NSTAGE) * STAGE_BYTES;
#pragma unroll
        for (int kk = 0; kk < KC; kk += 16) {
            // B fragments: n16 x k16 via ldmatrix.x4; tile nt0={r0,r2}, nt1={r1,r3}
            const int rb = wn * 16 + (lane & 15);
            const int cb = (kk >> 3) + (lane >> 4);
            uint32_t bh[4], bl[4];
            ldsm_x4(bh, st + ST_BH + sw_off(rb, cb));
            ldsm_x4(bl, st + ST_BL + sw_off(rb, cb));
#pragma unroll
            for (int mt = 0; mt < 4; mt++) {
                const int ra = wm * 64 + mt * 16 + (lane & 15);
                const int ca = (kk >> 3) + (lane >> 4);
                uint32_t ah[4], al[4];
                ldsm_x4(ah, st + ST_AH + sw_off(ra, ca));
                ldsm_x4(al, st + ST_AL + sw_off(ra, ca));
#pragma unroll
                for (int nt = 0; nt < 2; nt++) {
                    mma16816(acc[mt][nt], ah, bh[nt], bh[nt + 2]);  // hi*hi
                    mma16816(acc[mt][nt], ah, bl[nt], bl[nt + 2]);  // hi*lo
                    mma16816(acc[mt][nt], al, bh[nt], bh[nt + 2]);  // lo*hi
                }
            }
        }
        __syncthreads();
        if (i + 2 < NCHUNK) load_stage(i + 2);
    }

    // ---- epilogue: gates -> smem, then fused LSTM cell update ----
    float* sG = (float*)smem_raw;              // [128][SG_PITCH]
    const int lr = lane >> 2;
    const int lc = (lane & 3) * 2;
#pragma unroll
    for (int mt = 0; mt < 4; mt++) {
        const int r0 = wm * 64 + mt * 16 + lr;
#pragma unroll
        for (int nt = 0; nt < 2; nt++) {
            const int col = wn * 16 + nt * 8 + lc;
            sG[r0 * SG_PITCH + col]           = acc[mt][nt][0];
            sG[r0 * SG_PITCH + col + 1]       = acc[mt][nt][1];
            sG[(r0 + 8) * SG_PITCH + col]     = acc[mt][nt][2];
            sG[(r0 + 8) * SG_PITCH + col + 1] = acc[mt][nt][3];
        }
    }
    __syncthreads();

    __half* __restrict__ hh = g_hhi[dst];
    __half* __restrict__ hl = g_hlo[dst];
    const int jbase = blockIdx.x * 16;
#pragma unroll
    for (int e = 0; e < 8; e++) {
        int p = e * NTHREADS + tid;            // 0..2047
        int jj = p & 15;
        int b = p >> 4;
        int j = jbase + jj;
        float iv = sG[b * SG_PITCH + jj]      + g_bias[j];
        float fv = sG[b * SG_PITCH + 16 + jj] + g_bias[HH + j];
        float gv = sG[b * SG_PITCH + 32 + jj] + g_bias[2 * HH + j];
        float ov = sG[b * SG_PITCH + 48 + jj] + g_bias[3 * HH + j];
        float ig = sigmoidf_(iv);
        float fg = sigmoidf_(fv);
        float gg = tanhf(gv);
        float og = sigmoidf_(ov);
        int idx = b * HH + j;
        float cn = fg * g_c[idx] + ig * gg;
        g_c[idx] = cn;
        float hn = og * tanhf(cn);
        __half hi = __float2half_rn(hn);
        hh[idx] = hi;
        hl[idx] = __float2half_rn(hn - __half2float(hi));
    }
}

// ------------------------------------------------------------------
// Head: out[b,c] = h_last . W_out[c] + b_out[c]
// ------------------------------------------------------------------
__global__ void head_kernel(const float* __restrict__ W_out,
                            const float* __restrict__ b_out,
                            float* __restrict__ out, int src) {
    int b = blockIdx.x;
    int c = blockIdx.y;
    int lane = threadIdx.x;
    const __half* hh = g_hhi[src] + b * HH;
    const __half* hl = g_hlo[src] + b * HH;
    const float* w = W_out + c * HH;
    float sum = 0.0f;
    for (int k = lane; k < HH; k += 32) {
        float h = __half2float(hh[k]) + __half2float(hl[k]);
        sum = fmaf(h, w[k], sum);
    }
#pragma unroll
    for (int off = 16; off > 0; off >>= 1)
        sum += __shfl_down_sync(0xFFFFFFFFu, sum, off);
    if (lane == 0) out[b * NC + c] = sum + b_out[c];
}

// ------------------------------------------------------------------
// Host
// ------------------------------------------------------------------
extern "C" void kernel_launch(void* const* d_in, const int* in_sizes, int n_in,
                              void* d_out, int out_size) {
    const float* x     = (const float*)d_in[0];
    const float* h0    = (const float*)d_in[1];
    const float* c0    = (const float*)d_in[2];
    const float* W_ih  = (const float*)d_in[3];
    const float* W_hh  = (const float*)d_in[4];
    const float* b_ih  = (const float*)d_in[5];
    const float* b_hh  = (const float*)d_in[6];
    const float* W_out = (const float*)d_in[7];
    const float* b_out = (const float*)d_in[8];
    float* out = (float*)d_out;

    static int smem_set = 0;
    if (!smem_set) {
        cudaFuncSetAttribute(step_kernel,
                             cudaFuncAttributeMaxDynamicSharedMemorySize, SMEM_NEED);
        smem_set = 1;
    }

    prep_weights<<<(NTOT * KTOT + 255) / 256, 256>>>(W_ih, W_hh);
    prep_x<<<(SS * BB * II + 255) / 256, 256>>>(x);
    prep_state<<<(BB * HH + 255) / 256, 256>>>(h0, c0, b_ih, b_hh);

    for (int s = 0; s < SS; s++) {
        int src = s & 1;
        step_kernel<<<NCTA, NTHREADS, SMEM_NEED>>>(s, src, src ^ 1);
    }

    // 512 steps (even): final h in buffer 0
    head_kernel<<<dim3(BB, NC), 32>>>(W_out, b_out, out, 0);
}

// round 4
// speedup vs baseline: 4.4945x; 1.6594x over previous
#include <cuda_runtime.h>
#include <cuda_fp16.h>
#include <math.h>
#include <stdint.h>

// ------------------------------------------------------------------
// Problem constants
// ------------------------------------------------------------------
#define BB 128          // batch (GEMM M)
#define SS 512          // sequence length
#define II 256          // input size
#define HH 1024         // hidden size
#define NC 10           // classes
#define KTOT 1280       // K = HH + II
#define NTOT 4096       // 4*HH gate columns

#define NCTA 128        // persistent CTAs (<=148 SMs, all resident)
#define NTHREADS 256    // 8 warps
#define CTA_N 32        // gate columns per CTA (4 gates x 8 h-cols)
#define KC 64           // K elements per pipeline stage
#define NCHUNK (KTOT / KC)   // 20
#define NSTAGE 3

// Stage smem layout (bytes): Ah 16K | Al 16K | Bh 4K | Bl 4K = 40K
#define ST_AH 0
#define ST_AL 16384
#define ST_BH 32768
#define ST_BL 36864
#define STAGE_BYTES 40960
#define SMEM_NEED (NSTAGE * STAGE_BYTES)   // 120 KB -> 1 CTA/SM

// ------------------------------------------------------------------
// Persistent device scratch (allocation-free)
// ------------------------------------------------------------------
__device__ __align__(16) __half g_Whi[NTOT * KTOT];   // permuted [n'][k]
__device__ __align__(16) __half g_Wlo[NTOT * KTOT];
__device__ __align__(16) __half g_xhi[SS * BB * II];  // [s][b][i]
__device__ __align__(16) __half g_xlo[SS * BB * II];
__device__ __align__(16) __half g_hhi[2][BB * HH];
__device__ __align__(16) __half g_hlo[2][BB * HH];
__device__ float g_bias[NTOT];

// global barrier state (self-resetting; sense returns to 0 after even count)
__device__ volatile unsigned g_bar_count;
__device__ volatile unsigned g_bar_sense;

// ------------------------------------------------------------------
// PTX helpers (baseline compute_103 features only)
// ------------------------------------------------------------------
__device__ __forceinline__ uint32_t smem_u32(const void* p) {
    uint32_t a;
    asm("{ .reg .u64 t; cvta.to.shared.u64 t, %1; cvt.u32.u64 %0, t; }"
        : "=r"(a) : "l"(p));
    return a;
}
__device__ __forceinline__ void cp_async16(uint32_t saddr, const void* gaddr) {
    asm volatile("cp.async.cg.shared.global [%0], [%1], 16;"
                 :: "r"(saddr), "l"(gaddr) : "memory");
}
__device__ __forceinline__ void cp_commit() {
    asm volatile("cp.async.commit_group;" ::: "memory");
}
__device__ __forceinline__ void cp_wait1() {
    asm volatile("cp.async.wait_group 1;" ::: "memory");
}
__device__ __forceinline__ void cp_wait0() {
    asm volatile("cp.async.wait_group 0;" ::: "memory");
}
__device__ __forceinline__ void ldsm_x4(uint32_t* r, uint32_t addr) {
    asm volatile("ldmatrix.sync.aligned.m8n8.x4.shared.b16 {%0,%1,%2,%3}, [%4];"
                 : "=r"(r[0]), "=r"(r[1]), "=r"(r[2]), "=r"(r[3]) : "r"(addr));
}
__device__ __forceinline__ void mma16816(float* d, const uint32_t* a,
                                         uint32_t b0, uint32_t b1) {
    asm volatile(
        "mma.sync.aligned.m16n8k16.row.col.f32.f16.f16.f32 "
        "{%0,%1,%2,%3}, {%4,%5,%6,%7}, {%8,%9}, {%0,%1,%2,%3};"
        : "+f"(d[0]), "+f"(d[1]), "+f"(d[2]), "+f"(d[3])
        : "r"(a[0]), "r"(a[1]), "r"(a[2]), "r"(a[3]), "r"(b0), "r"(b1));
}
__device__ __forceinline__ float sigmoidf_(float v) {
    return 1.0f / (1.0f + expf(-v));
}
// swizzled smem byte offset within a [rows][64 half] tile (128B rows)
__device__ __forceinline__ uint32_t sw_off(int r, int c) {   // c = 16B chunk 0..7
    return (uint32_t)(r * 128 + ((c ^ (r & 7)) << 4));
}

// ------------------------------------------------------------------
// Prep kernels
// ------------------------------------------------------------------
// Permuted, split weight matrix Wp[n'][k]:
//   n' = cta*32 + g*8 + jj  ->  weight row = g*1024 + cta*8 + jj
//   k < 1024: W_hh[row][k]; else W_ih[row][k-1024]
__global__ void prep_weights(const float* __restrict__ W_ih,
                             const float* __restrict__ W_hh) {
    int idx = blockIdx.x * blockDim.x + threadIdx.x;
    if (idx >= NTOT * KTOT) return;
    int n = idx / KTOT;
    int k = idx - n * KTOT;
    int cta = n >> 5;
    int g = (n >> 3) & 3;
    int jj = n & 7;
    int row = g * HH + cta * 8 + jj;
    float v = (k < HH) ? W_hh[row * HH + k] : W_ih[row * II + (k - HH)];
    __half hi = __float2half_rn(v);
    __half lo = __float2half_rn(v - __half2float(hi));
    g_Whi[idx] = hi;
    g_Wlo[idx] = lo;
}

__global__ void prep_x(const float* __restrict__ x) {
    int idx = blockIdx.x * blockDim.x + threadIdx.x;
    if (idx >= SS * BB * II) return;
    int s = idx / (BB * II);
    int r = idx - s * (BB * II);
    int b = r / II;
    int i = r - b * II;
    float v = x[(b * SS + s) * II + i];
    __half hi = __float2half_rn(v);
    __half lo = __float2half_rn(v - __half2float(hi));
    g_xhi[idx] = hi;
    g_xlo[idx] = lo;
}

__global__ void prep_state(const float* __restrict__ h0,
                           const float* __restrict__ b_ih,
                           const float* __restrict__ b_hh) {
    int idx = blockIdx.x * blockDim.x + threadIdx.x;
    if (idx < BB * HH) {
        float v = h0[idx];
        __half hi = __float2half_rn(v);
        __half lo = __float2half_rn(v - __half2float(hi));
        g_hhi[0][idx] = hi;
        g_hlo[0][idx] = lo;
    }
    if (idx < NTOT) g_bias[idx] = b_ih[idx] + b_hh[idx];
}

// ------------------------------------------------------------------
// Persistent LSTM kernel: all 512 steps, grid-wide sense barrier.
//   CTA tile: M=128 x N=32 (permuted: 4 gates x 8 h-cols)
//   Warp tile: m16 x n32 -> each thread's fragments hold all 4 gates
//   for its (b, hcol) cells => register-only cell update; c in registers
//   for the whole sequence.
// ------------------------------------------------------------------
__global__ void __launch_bounds__(NTHREADS, 1) lstm_persistent(
    const float* __restrict__ c0in)
{
    extern __shared__ char smem_raw[];
    const uint32_t sb = smem_u32(smem_raw);

    const int tid = threadIdx.x;
    const int wid = tid >> 5;
    const int lane = tid & 31;
    const int n0 = blockIdx.x * CTA_N;     // permuted gate-column base
    const int jb = blockIdx.x * 8;         // h-column base
    const int frow = lane >> 2;            // fragment row 0..7
    const int fcol = (lane & 3) * 2;       // fragment col (even)
    const int b0 = wid * 16 + frow;

    // hoisted constants: biases (8) and cell state (4) live in registers
    float bias_r[4][2];
#pragma unroll
    for (int g = 0; g < 4; g++)
#pragma unroll
        for (int e = 0; e < 2; e++)
            bias_r[g][e] = g_bias[g * HH + jb + fcol + e];

    float creg[4];
    creg[0] = c0in[b0 * HH + jb + fcol];
    creg[1] = c0in[b0 * HH + jb + fcol + 1];
    creg[2] = c0in[(b0 + 8) * HH + jb + fcol];
    creg[3] = c0in[(b0 + 8) * HH + jb + fcol + 1];

    unsigned sense = 0;

    for (int s = 0; s < SS; s++) {
        const __half* __restrict__ hin_hi = g_hhi[s & 1];
        const __half* __restrict__ hin_lo = g_hlo[s & 1];
        __half* __restrict__ hout_hi = g_hhi[(s & 1) ^ 1];
        __half* __restrict__ hout_lo = g_hlo[(s & 1) ^ 1];

        // ---- stage loader ----
        auto load_stage = [&](int chunk) {
            const uint32_t st = sb + (uint32_t)(chunk % NSTAGE) * STAGE_BYTES;
            const int k0 = chunk * KC;
#pragma unroll
            for (int i = 0; i < 4; i++) {           // A: 128 x 64 halves
                int id = tid + i * NTHREADS;
                int r = id >> 3;
                int c = id & 7;
                uint32_t d = sw_off(r, c);
                if (chunk < 16) {
                    cp_async16(st + ST_AH + d, hin_hi + r * HH + k0 + c * 8);
                    cp_async16(st + ST_AL + d, hin_lo + r * HH + k0 + c * 8);
                } else {
                    size_t off = ((size_t)s * BB + r) * II + (k0 - HH) + c * 8;
                    cp_async16(st + ST_AH + d, g_xhi + off);
                    cp_async16(st + ST_AL + d, g_xlo + off);
                }
            }
            {                                        // B: 32 x 64 halves
                int r = tid >> 3;
                int c = tid & 7;
                if (r < CTA_N) {
                    uint32_t d = sw_off(r, c);
                    size_t off = (size_t)(n0 + r) * KTOT + k0 + c * 8;
                    cp_async16(st + ST_BH + d, g_Whi + off);
                    cp_async16(st + ST_BL + d, g_Wlo + off);
                }
            }
            cp_commit();
        };

        load_stage(0);
        load_stage(1);

        float acc[4][4];
#pragma unroll
        for (int g = 0; g < 4; g++)
#pragma unroll
            for (int e = 0; e < 4; e++) acc[g][e] = 0.0f;

        for (int i = 0; i < NCHUNK; i++) {
            if (i == NCHUNK - 1) cp_wait0(); else cp_wait1();
            __syncthreads();
            if (i + 2 < NCHUNK) load_stage(i + 2);

            const uint32_t st = sb + (uint32_t)(i % NSTAGE) * STAGE_BYTES;
#pragma unroll
            for (int kk = 0; kk < KC; kk += 16) {
                const int ck = (kk >> 3) + (lane >> 4);
                const int ra = wid * 16 + (lane & 15);
                const int rb = lane & 15;
                uint32_t ah[4], al[4], bh0[4], bh1[4], bl0[4], bl1[4];
                ldsm_x4(ah, st + ST_AH + sw_off(ra, ck));
                ldsm_x4(al, st + ST_AL + sw_off(ra, ck));
                ldsm_x4(bh0, st + ST_BH + sw_off(rb, ck));
                ldsm_x4(bh1, st + ST_BH + sw_off(rb + 16, ck));
                ldsm_x4(bl0, st + ST_BL + sw_off(rb, ck));
                ldsm_x4(bl1, st + ST_BL + sw_off(rb + 16, ck));

                mma16816(acc[0], ah, bh0[0], bh0[2]);   // hi*hi
                mma16816(acc[1], ah, bh0[1], bh0[3]);
                mma16816(acc[2], ah, bh1[0], bh1[2]);
                mma16816(acc[3], ah, bh1[1], bh1[3]);
                mma16816(acc[0], ah, bl0[0], bl0[2]);   // hi*lo
                mma16816(acc[1], ah, bl0[1], bl0[3]);
                mma16816(acc[2], ah, bl1[0], bl1[2]);
                mma16816(acc[3], ah, bl1[1], bl1[3]);
                mma16816(acc[0], al, bh0[0], bh0[2]);   // lo*hi
                mma16816(acc[1], al, bh0[1], bh0[3]);
                mma16816(acc[2], al, bh1[0], bh1[2]);
                mma16816(acc[3], al, bh1[1], bh1[3]);
            }
        }

        // ---- register-only LSTM cell update ----
        // fragment e: e=0 -> (b0, fcol), e=1 -> (b0, fcol+1),
        //             e=2 -> (b0+8, fcol), e=3 -> (b0+8, fcol+1)
#pragma unroll
        for (int e = 0; e < 4; e++) {
            float iv = acc[0][e] + bias_r[0][e & 1];
            float fv = acc[1][e] + bias_r[1][e & 1];
            float gv = acc[2][e] + bias_r[2][e & 1];
            float ov = acc[3][e] + bias_r[3][e & 1];
            float ig = sigmoidf_(iv);
            float fg = sigmoidf_(fv);
            float gg = tanhf(gv);
            float og = sigmoidf_(ov);
            float cn = fg * creg[e] + ig * gg;
            creg[e] = cn;
            float hn = og * tanhf(cn);
            int b = b0 + ((e >> 1) << 3);
            int idx = b * HH + jb + fcol + (e & 1);
            __half hi = __float2half_rn(hn);
            hout_hi[idx] = hi;
            hout_lo[idx] = __float2half_rn(hn - __half2float(hi));
        }
        __threadfence();

        // ---- grid-wide sense-reversing barrier ----
        __syncthreads();
        if (tid == 0) {
            unsigned want = sense ^ 1;
            unsigned arr = atomicAdd((unsigned*)&g_bar_count, 1u);
            if (arr == NCTA - 1) {
                g_bar_count = 0;
                __threadfence();
                g_bar_sense = want;
            } else {
                while (g_bar_sense != want) __nanosleep(64);
            }
            __threadfence();
        }
        __syncthreads();
        sense ^= 1;
    }
}

// ------------------------------------------------------------------
// Head: out[b,c] = h_last . W_out[c] + b_out[c]
// ------------------------------------------------------------------
__global__ void head_kernel(const float* __restrict__ W_out,
                            const float* __restrict__ b_out,
                            float* __restrict__ out) {
    int b = blockIdx.x;
    int c = blockIdx.y;
    int lane = threadIdx.x;
    const __half* hh = g_hhi[0] + b * HH;   // 512 steps even -> buffer 0
    const __half* hl = g_hlo[0] + b * HH;
    const float* w = W_out + c * HH;
    float sum = 0.0f;
    for (int k = lane; k < HH; k += 32) {
        float h = __half2float(hh[k]) + __half2float(hl[k]);
        sum = fmaf(h, w[k], sum);
    }
#pragma unroll
    for (int off = 16; off > 0; off >>= 1)
        sum += __shfl_down_sync(0xFFFFFFFFu, sum, off);
    if (lane == 0) out[b * NC + c] = sum + b_out[c];
}

// ------------------------------------------------------------------
// Host
// ------------------------------------------------------------------
extern "C" void kernel_launch(void* const* d_in, const int* in_sizes, int n_in,
                              void* d_out, int out_size) {
    const float* x     = (const float*)d_in[0];
    const float* h0    = (const float*)d_in[1];
    const float* c0    = (const float*)d_in[2];
    const float* W_ih  = (const float*)d_in[3];
    const float* W_hh  = (const float*)d_in[4];
    const float* b_ih  = (const float*)d_in[5];
    const float* b_hh  = (const float*)d_in[6];
    const float* W_out = (const float*)d_in[7];
    const float* b_out = (const float*)d_in[8];
    float* out = (float*)d_out;

    cudaFuncSetAttribute(lstm_persistent,
                         cudaFuncAttributeMaxDynamicSharedMemorySize, SMEM_NEED);

    prep_weights<<<(NTOT * KTOT + 255) / 256, 256>>>(W_ih, W_hh);
    prep_x<<<(SS * BB * II + 255) / 256, 256>>>(x);
    prep_state<<<(BB * HH + 255) / 256, 256>>>(h0, b_ih, b_hh);

    lstm_persistent<<<NCTA, NTHREADS, SMEM_NEED>>>(c0);

    head_kernel<<<dim3(BB, NC), 32>>>(W_out, b_out, out);
}

// round 5
// speedup vs baseline: 4.6108x; 1.0259x over previous
#include <cuda_runtime.h>
#include <cuda_fp16.h>
#include <math.h>
#include <stdint.h>

// ------------------------------------------------------------------
// Problem constants
// ------------------------------------------------------------------
#define BB 128          // batch (GEMM M)
#define SS 512          // sequence length
#define II 256          // input size
#define HH 1024         // hidden size
#define NC 10           // classes
#define KTOT 1280       // K = HH + II
#define NTOT 4096       // 4*HH gate columns

#define NCTA 128        // 2 batch-groups x 64 n-tiles, persistent
#define NTHREADS 256    // 8 warps: 4 in M x 2 in N
#define CTA_M 64        // batch rows per CTA
#define CTA_N 64        // gate columns per CTA (2 x [4 gates x 8 h-cols])
#define KC 64           // K elements per pipeline stage
#define NCHUNK (KTOT / KC)   // 20 (4 x-chunks + 16 h-chunks)
#define NSTAGE 6
#define AHEAD 5

// Stage smem layout (bytes): Ah 8K | Al 8K | Bh 8K | Bl 8K = 32K
#define ST_AH 0
#define ST_AL 8192
#define ST_BH 16384
#define ST_BL 24576
#define STAGE_BYTES 32768
#define SMEM_NEED (NSTAGE * STAGE_BYTES)   // 192 KB -> 1 CTA/SM

// ------------------------------------------------------------------
// Persistent device scratch (allocation-free)
// ------------------------------------------------------------------
__device__ __align__(16) __half g_Whi[NTOT * KTOT];   // permuted [n'][k]
__device__ __align__(16) __half g_Wlo[NTOT * KTOT];
__device__ __align__(16) __half g_xhi[SS * BB * II];  // [s][b][i]
__device__ __align__(16) __half g_xlo[SS * BB * II];
__device__ __align__(16) __half g_hhi[2][BB * HH];
__device__ __align__(16) __half g_hlo[2][BB * HH];
__device__ float g_bias[NTOT];

// per-group barrier state (self-resetting across replays: 512 flips = even)
__device__ volatile unsigned g_cnt[2];
__device__ volatile unsigned g_sns[2];

// ------------------------------------------------------------------
// PTX helpers (baseline compute_103 features only)
// ------------------------------------------------------------------
__device__ __forceinline__ uint32_t smem_u32(const void* p) {
    uint32_t a;
    asm("{ .reg .u64 t; cvta.to.shared.u64 t, %1; cvt.u32.u64 %0, t; }"
        : "=r"(a) : "l"(p));
    return a;
}
__device__ __forceinline__ void cp_async16(uint32_t saddr, const void* gaddr) {
    asm volatile("cp.async.cg.shared.global [%0], [%1], 16;"
                 :: "r"(saddr), "l"(gaddr) : "memory");
}
__device__ __forceinline__ void cp_commit() {
    asm volatile("cp.async.commit_group;" ::: "memory");
}
__device__ __forceinline__ void cp_wait_n(int n) {
    switch (n) {
    case 0: asm volatile("cp.async.wait_group 0;" ::: "memory"); break;
    case 1: asm volatile("cp.async.wait_group 1;" ::: "memory"); break;
    case 2: asm volatile("cp.async.wait_group 2;" ::: "memory"); break;
    case 3: asm volatile("cp.async.wait_group 3;" ::: "memory"); break;
    default: asm volatile("cp.async.wait_group 4;" ::: "memory"); break;
    }
}
__device__ __forceinline__ void ldsm_x4(uint32_t* r, uint32_t addr) {
    asm volatile("ldmatrix.sync.aligned.m8n8.x4.shared.b16 {%0,%1,%2,%3}, [%4];"
                 : "=r"(r[0]), "=r"(r[1]), "=r"(r[2]), "=r"(r[3]) : "r"(addr));
}
__device__ __forceinline__ void mma16816(float* d, const uint32_t* a,
                                         uint32_t b0, uint32_t b1) {
    asm volatile(
        "mma.sync.aligned.m16n8k16.row.col.f32.f16.f16.f32 "
        "{%0,%1,%2,%3}, {%4,%5,%6,%7}, {%8,%9}, {%0,%1,%2,%3};"
        : "+f"(d[0]), "+f"(d[1]), "+f"(d[2]), "+f"(d[3])
        : "r"(a[0]), "r"(a[1]), "r"(a[2]), "r"(a[3]), "r"(b0), "r"(b1));
}
__device__ __forceinline__ float sigmoidf_(float v) {
    return 1.0f / (1.0f + expf(-v));
}
// swizzled smem byte offset within a [rows][64 half] tile (128B rows)
__device__ __forceinline__ uint32_t sw_off(int r, int c) {   // c = 16B chunk 0..7
    return (uint32_t)(r * 128 + ((c ^ (r & 7)) << 4));
}

// ------------------------------------------------------------------
// Prep kernels
// ------------------------------------------------------------------
// Permuted, split weight matrix Wp[n'][k]:
//   n' = nb*64 + wn*32 + g*8 + jj  ->  weight row = g*1024 + nb*16 + wn*8 + jj
//   k < 1024: W_hh[row][k]; else W_ih[row][k-1024]
__global__ void prep_weights(const float* __restrict__ W_ih,
                             const float* __restrict__ W_hh) {
    int idx = blockIdx.x * blockDim.x + threadIdx.x;
    if (idx >= NTOT * KTOT) return;
    int n = idx / KTOT;
    int k = idx - n * KTOT;
    int nb = n >> 6;
    int r6 = n & 63;
    int wn = r6 >> 5;
    int g = (r6 >> 3) & 3;
    int jj = r6 & 7;
    int row = g * HH + nb * 16 + wn * 8 + jj;
    float v = (k < HH) ? W_hh[row * HH + k] : W_ih[row * II + (k - HH)];
    __half hi = __float2half_rn(v);
    __half lo = __float2half_rn(v - __half2float(hi));
    g_Whi[idx] = hi;
    g_Wlo[idx] = lo;
}

__global__ void prep_x(const float* __restrict__ x) {
    int idx = blockIdx.x * blockDim.x + threadIdx.x;
    if (idx >= SS * BB * II) return;
    int s = idx / (BB * II);
    int r = idx - s * (BB * II);
    int b = r / II;
    int i = r - b * II;
    float v = x[(b * SS + s) * II + i];
    __half hi = __float2half_rn(v);
    __half lo = __float2half_rn(v - __half2float(hi));
    g_xhi[idx] = hi;
    g_xlo[idx] = lo;
}

__global__ void prep_state(const float* __restrict__ h0,
                           const float* __restrict__ b_ih,
                           const float* __restrict__ b_hh) {
    int idx = blockIdx.x * blockDim.x + threadIdx.x;
    if (idx < BB * HH) {
        float v = h0[idx];
        __half hi = __float2half_rn(v);
        __half lo = __float2half_rn(v - __half2float(hi));
        g_hhi[0][idx] = hi;
        g_hlo[0][idx] = lo;
    }
    if (idx < NTOT) g_bias[idx] = b_ih[idx] + b_hh[idx];
}

// ------------------------------------------------------------------
// Persistent LSTM kernel: all 512 steps.
//   CTA tile: M=64 (one batch-group half) x N=64 (permuted gates)
//   Warps: 4 in M x 2 in N; warp tile m16 x n32 = 4 gates x 8 h-cols
//   => register-only cell update; c in registers for the whole sequence.
//   Two independent grid barriers (one per batch group of 64 CTAs);
//   x-chunks (h-independent) are prefetched before the barrier wait.
// ------------------------------------------------------------------
__global__ void __launch_bounds__(NTHREADS, 1) lstm_persistent(
    const float* __restrict__ c0in)
{
    extern __shared__ char smem_raw[];
    const uint32_t sb = smem_u32(smem_raw);

    const int tid = threadIdx.x;
    const int wid = tid >> 5;
    const int lane = tid & 31;
    const int grp = blockIdx.x & 1;        // batch group (rows grp*64..+63)
    const int nb = blockIdx.x >> 1;        // n-tile index (0..63)
    const int gb = grp * CTA_M;            // global batch base
    const int wm = wid & 3;                // 0..3 : M warp group (16 rows)
    const int wn = wid >> 2;               // 0..1 : N warp group (32 cols)
    const int frow = lane >> 2;            // fragment row 0..7
    const int fcol = (lane & 3) * 2;       // fragment col (even) 0..6
    const int b0 = gb + wm * 16 + frow;    // global batch row of frag row 0
    const int jbw = nb * 16 + wn * 8;      // h-column base for this warp

    // hoisted constants: biases (8) and cell state (4) live in registers
    float bias_r[4][2];
#pragma unroll
    for (int g = 0; g < 4; g++)
#pragma unroll
        for (int e = 0; e < 2; e++)
            bias_r[g][e] = g_bias[g * HH + jbw + fcol + e];

    float creg[4];
    creg[0] = c0in[b0 * HH + jbw + fcol];
    creg[1] = c0in[b0 * HH + jbw + fcol + 1];
    creg[2] = c0in[(b0 + 8) * HH + jbw + fcol];
    creg[3] = c0in[(b0 + 8) * HH + jbw + fcol + 1];

    for (int s = 0; s < SS; s++) {
        const __half* __restrict__ hin_hi = g_hhi[s & 1];
        const __half* __restrict__ hin_lo = g_hlo[s & 1];
        __half* __restrict__ hout_hi = g_hhi[(s & 1) ^ 1];
        __half* __restrict__ hout_lo = g_hlo[(s & 1) ^ 1];

        // chunk order: ci 0..3 -> x (ka 16..19), ci 4..19 -> h (ka 0..15)
        auto load_stage = [&](int ci) {
            const uint32_t st = sb + (uint32_t)(ci % NSTAGE) * STAGE_BYTES;
            const int ka = (ci < 4) ? (16 + ci) : (ci - 4);
            const int k0 = ka * KC;
            // A: 64 rows x 64 halves (hi & lo): 2x 16B chunks per thread each
#pragma unroll
            for (int i = 0; i < 2; i++) {
                int id = tid + i * NTHREADS;   // 0..511
                int r = id >> 3;               // local batch row 0..63
                int c = id & 7;                // 16B chunk in row
                uint32_t d = sw_off(r, c);
                if (ka < 16) {
                    cp_async16(st + ST_AH + d, hin_hi + (gb + r) * HH + k0 + c * 8);
                    cp_async16(st + ST_AL + d, hin_lo + (gb + r) * HH + k0 + c * 8);
                } else {
                    size_t off = ((size_t)s * BB + gb + r) * II + (k0 - HH) + c * 8;
                    cp_async16(st + ST_AH + d, g_xhi + off);
                    cp_async16(st + ST_AL + d, g_xlo + off);
                }
            }
            // B: 64 rows x 64 halves (hi & lo)
#pragma unroll
            for (int i = 0; i < 2; i++) {
                int id = tid + i * NTHREADS;
                int r = id >> 3;
                int c = id & 7;
                uint32_t d = sw_off(r, c);
                size_t off = (size_t)(nb * CTA_N + r) * KTOT + k0 + c * 8;
                cp_async16(st + ST_BH + d, g_Whi + off);
                cp_async16(st + ST_BL + d, g_Wlo + off);
            }
            cp_commit();
        };

        // prefetch x chunks (independent of h) before the barrier wait
        load_stage(0); load_stage(1); load_stage(2); load_stage(3);

        // wait for previous step's h (skip at s=0: h0 ready by stream order)
        if (s > 0) {
            if (tid == 0) {
                while (g_sns[grp] != (unsigned)(s & 1)) __nanosleep(32);
                __threadfence();
            }
            __syncthreads();
        }
        load_stage(4);

        float acc[4][4];
#pragma unroll
        for (int g = 0; g < 4; g++)
#pragma unroll
            for (int e = 0; e < 4; e++) acc[g][e] = 0.0f;

        for (int i = 0; i < NCHUNK; i++) {
            int rem = NCHUNK - 1 - i;
            cp_wait_n(rem < 4 ? rem : 4);
            __syncthreads();
            if (i + AHEAD < NCHUNK) load_stage(i + AHEAD);

            const uint32_t st = sb + (uint32_t)(i % NSTAGE) * STAGE_BYTES;
#pragma unroll
            for (int kk = 0; kk < KC; kk += 16) {
                const int ck = (kk >> 3) + (lane >> 4);
                const int ra = wm * 16 + (lane & 15);
                const int rb = wn * 32 + (lane & 15);
                uint32_t ah[4], al[4], bh0[4], bh1[4], bl0[4], bl1[4];
                ldsm_x4(ah, st + ST_AH + sw_off(ra, ck));
                ldsm_x4(al, st + ST_AL + sw_off(ra, ck));
                ldsm_x4(bh0, st + ST_BH + sw_off(rb, ck));
                ldsm_x4(bh1, st + ST_BH + sw_off(rb + 16, ck));
                ldsm_x4(bl0, st + ST_BL + sw_off(rb, ck));
                ldsm_x4(bl1, st + ST_BL + sw_off(rb + 16, ck));

                mma16816(acc[0], ah, bh0[0], bh0[2]);   // hi*hi
                mma16816(acc[1], ah, bh0[1], bh0[3]);
                mma16816(acc[2], ah, bh1[0], bh1[2]);
                mma16816(acc[3], ah, bh1[1], bh1[3]);
                mma16816(acc[0], ah, bl0[0], bl0[2]);   // hi*lo
                mma16816(acc[1], ah, bl0[1], bl0[3]);
                mma16816(acc[2], ah, bl1[0], bl1[2]);
                mma16816(acc[3], ah, bl1[1], bl1[3]);
                mma16816(acc[0], al, bh0[0], bh0[2]);   // lo*hi
                mma16816(acc[1], al, bh0[1], bh0[3]);
                mma16816(acc[2], al, bh1[0], bh1[2]);
                mma16816(acc[3], al, bh1[1], bh1[3]);
            }
        }

        // ---- register-only LSTM cell update ----
#pragma unroll
        for (int e = 0; e < 4; e++) {
            float iv = acc[0][e] + bias_r[0][e & 1];
            float fv = acc[1][e] + bias_r[1][e & 1];
            float gv = acc[2][e] + bias_r[2][e & 1];
            float ov = acc[3][e] + bias_r[3][e & 1];
            float ig = sigmoidf_(iv);
            float fg = sigmoidf_(fv);
            float gg = tanhf(gv);
            float og = sigmoidf_(ov);
            float cn = fg * creg[e] + ig * gg;
            creg[e] = cn;
            float hn = og * tanhf(cn);
            int b = b0 + ((e >> 1) << 3);
            int idx = b * HH + jbw + fcol + (e & 1);
            __half hi = __float2half_rn(hn);
            hout_hi[idx] = hi;
            hout_lo[idx] = __float2half_rn(hn - __half2float(hi));
        }

        // ---- arrive on group barrier (wait happens next iteration) ----
        __syncthreads();                 // all h writes of this CTA done
        if (tid == 0) {
            __threadfence();             // publish h
            unsigned a = atomicAdd((unsigned*)&g_cnt[grp], 1u);
            if (a == 63) {
                g_cnt[grp] = 0;
                __threadfence();
                g_sns[grp] = (unsigned)((s + 1) & 1);
            }
        }
    }
}

// ------------------------------------------------------------------
// Head: out[b,c] = h_last . W_out[c] + b_out[c]
// ------------------------------------------------------------------
__global__ void head_kernel(const float* __restrict__ W_out,
                            const float* __restrict__ b_out,
                            float* __restrict__ out) {
    int b = blockIdx.x;
    int c = blockIdx.y;
    int lane = threadIdx.x;
    const __half* hh = g_hhi[0] + b * HH;   // 512 steps even -> buffer 0
    const __half* hl = g_hlo[0] + b * HH;
    const float* w = W_out + c * HH;
    float sum = 0.0f;
    for (int k = lane; k < HH; k += 32) {
        float h = __half2float(hh[k]) + __half2float(hl[k]);
        sum = fmaf(h, w[k], sum);
    }
#pragma unroll
    for (int off = 16; off > 0; off >>= 1)
        sum += __shfl_down_sync(0xFFFFFFFFu, sum, off);
    if (lane == 0) out[b * NC + c] = sum + b_out[c];
}

// ------------------------------------------------------------------
// Host
// ------------------------------------------------------------------
extern "C" void kernel_launch(void* const* d_in, const int* in_sizes, int n_in,
                              void* d_out, int out_size) {
    const float* x     = (const float*)d_in[0];
    const float* h0    = (const float*)d_in[1];
    const float* c0    = (const float*)d_in[2];
    const float* W_ih  = (const float*)d_in[3];
    const float* W_hh  = (const float*)d_in[4];
    const float* b_ih  = (const float*)d_in[5];
    const float* b_hh  = (const float*)d_in[6];
    const float* W_out = (const float*)d_in[7];
    const float* b_out = (const float*)d_in[8];
    float* out = (float*)d_out;

    cudaFuncSetAttribute(lstm_persistent,
                         cudaFuncAttributeMaxDynamicSharedMemorySize, SMEM_NEED);

    prep_weights<<<(NTOT * KTOT + 255) / 256, 256>>>(W_ih, W_hh);
    prep_x<<<(SS * BB * II + 255) / 256, 256>>>(x);
    prep_state<<<(BB * HH + 255) / 256, 256>>>(h0, b_ih, b_hh);

    lstm_persistent<<<NCTA, NTHREADS, SMEM_NEED>>>(c0);

    head_kernel<<<dim3(BB, NC), 32>>>(W_out, b_out, out);
}